// round 2
// baseline (speedup 1.0000x reference)
#include <cuda_runtime.h>

// out[b,o] = sum_{i<64, l<32} obs[b,i,l,o] * ctx[b, 31-l, i]
// obs[b] flattened over (i,l,o) is contiguous: offset = p*64 + o, p = i*32 + l.
// One CTA per b. 256 threads = 16 groups x 16 lanes; lane owns 4 o-values (float4).

#define B_DIM 2048
#define R_DIM 32
#define O_DIM 64
#define PAIRS 2048           // 64*32
#define GROUPS 16
#define PAIRS_PER_GROUP (PAIRS / GROUPS)   // 128

__global__ __launch_bounds__(256, 8)
void cnnkf_kernel(const float* __restrict__ ctx,
                  const float* __restrict__ obs,
                  float* __restrict__ out) {
    __shared__ float s_ctx[R_DIM * O_DIM];       // 8 KB: ctx[b] row-major [r][i]
    __shared__ float s_part[GROUPS][O_DIM];      // 4 KB: per-group partial sums

    const int b   = blockIdx.x;
    const int tid = threadIdx.x;

    const float* __restrict__ ctx_b = ctx + (size_t)b * (R_DIM * O_DIM);
    const float* __restrict__ obs_b = obs + (size_t)b * (size_t)(PAIRS * O_DIM);

    // Stage context slice (2048 floats) into smem, coalesced.
    #pragma unroll
    for (int k = 0; k < (R_DIM * O_DIM) / 256; k++) {
        s_ctx[k * 256 + tid] = ctx_b[k * 256 + tid];
    }
    __syncthreads();

    const int group = tid >> 4;   // 0..15
    const int olane = tid & 15;   // 0..15  -> o = olane*4 .. olane*4+3

    float4 acc = make_float4(0.f, 0.f, 0.f, 0.f);

    // float4 view: element (p, o4) at index p*16 + o4
    const float4* __restrict__ base = reinterpret_cast<const float4*>(obs_b);

    #pragma unroll 8
    for (int j = 0; j < PAIRS_PER_GROUP; j++) {
        const int p = j * GROUPS + group;          // warp (2 groups) -> contiguous 512B
        const float4 v = base[p * 16 + olane];
        const int l = p & 31;
        const int i = p >> 5;
        const float c = s_ctx[(31 - l) * O_DIM + i];   // broadcast within group
        acc.x = fmaf(c, v.x, acc.x);
        acc.y = fmaf(c, v.y, acc.y);
        acc.z = fmaf(c, v.z, acc.z);
        acc.w = fmaf(c, v.w, acc.w);
    }

    // Write partials
    *reinterpret_cast<float4*>(&s_part[group][olane * 4]) = acc;
    __syncthreads();

    // Cross-group reduction: 64 threads, one per o
    if (tid < O_DIM) {
        float s = 0.f;
        #pragma unroll
        for (int g = 0; g < GROUPS; g++) s += s_part[g][tid];
        out[(size_t)b * O_DIM + tid] = s;
    }
}

extern "C" void kernel_launch(void* const* d_in, const int* in_sizes, int n_in,
                              void* d_out, int out_size) {
    const float* ctx = (const float*)d_in[0];   // context      (B, R, O)
    const float* obs = (const float*)d_in[1];   // observation  (B, O, R, O)
    float* out = (float*)d_out;                  // (B, O)

    cnnkf_kernel<<<B_DIM, 256>>>(ctx, obs, out);
}